// round 4
// baseline (speedup 1.0000x reference)
#include <cuda_runtime.h>
#include <cuda_bf16.h>
#include <math.h>
#include <stdint.h>

#define BB 2
#define NROI 625
#define NTOT 1250
#define CC 512
#define DD 25088            // 512*49
#define H1 200
#define H2 100
#define KC 17
#define NKEY 2402
#define TOTKEY 4804
#define MAXROWS 1250
#define KSPLIT 49
#define KCHUNK 512
#define NPREP 128           // prep blocks in fused0

// ---------------- scratch ----------------
__device__ float g_A[(size_t)MAXROWS * DD];
__device__ float g_P[(size_t)KSPLIT * MAXROWS * H1];
__device__ float g_W[(size_t)H1 * DD];     // tf32-rounded w1
__device__ float g_F[BB * CC * 49];        // tf32-rounded cfeats
__device__ float g_out85_unused[1];
__device__ int   g_keyOfRow[TOTKEY];
__device__ int   g_roiRow[NTOT];
__device__ int   g_M[1];

// ---------------- tf32 helpers ----------------
__device__ __forceinline__ float tf32r(float x) {
    uint32_t u;
    asm("cvt.rna.tf32.f32 %0, %1;" : "=r"(u) : "f"(x));
    return __uint_as_float(u);
}
__device__ __forceinline__ void cvt4(float4& v) {
    v.x = tf32r(v.x); v.y = tf32r(v.y); v.z = tf32r(v.z); v.w = tf32r(v.w);
}
__device__ __forceinline__ void mma_tf32(float& d0, float& d1, float& d2, float& d3,
                                         uint32_t a0, uint32_t a1, uint32_t a2, uint32_t a3,
                                         uint32_t b0, uint32_t b1) {
    asm volatile(
        "mma.sync.aligned.m16n8k8.row.col.f32.tf32.tf32.f32 "
        "{%0,%1,%2,%3}, {%4,%5,%6,%7}, {%8,%9}, {%0,%1,%2,%3};\n"
        : "+f"(d0), "+f"(d1), "+f"(d2), "+f"(d3)
        : "r"(a0), "r"(a1), "r"(a2), "r"(a3), "r"(b0), "r"(b1));
}

// ---------------- fused kernel 0: control (block 0) + weight/feature prep ----------------
__global__ void __launch_bounds__(1024) fused0_kernel(const float* __restrict__ regcls,
                                                      const float* __restrict__ wan,
                                                      const float* __restrict__ han,
                                                      const float* __restrict__ xan,
                                                      const float* __restrict__ yan,
                                                      const float* __restrict__ w1,
                                                      const float* __restrict__ cf) {
    const int tid = threadIdx.x;
    if (blockIdx.x != 0) {
        // ---- prep path: tf32-round w1 and cfeats ----
        int pb = blockIdx.x - 1;
        const size_t NW4 = (size_t)H1 * DD / 4;      // 1,254,400
        for (size_t i = (size_t)pb * 1024 + tid; i < NW4; i += (size_t)NPREP * 1024) {
            float4 v = reinterpret_cast<const float4*>(w1)[i];
            cvt4(v);
            reinterpret_cast<float4*>(g_W)[i] = v;
        }
        const int NF4 = BB * CC * 49 / 4;            // 12,544
        for (int i = pb * 1024 + tid; i < NF4; i += NPREP * 1024) {
            float4 v = reinterpret_cast<const float4*>(cf)[i];
            cvt4(v);
            reinterpret_cast<float4*>(g_F)[i] = v;
        }
        return;
    }
    // ---- control path: boxes + dedup + scan, all in one block ----
    __shared__ int s_used[TOTKEY];
    __shared__ int s_key[NTOT];
    __shared__ int wsum[32];
    for (int i = tid; i < TOTKEY; i += 1024) s_used[i] = 0;
    __syncthreads();
#pragma unroll
    for (int u = 0; u < 2; u++) {
        int idx = tid + u * 1024;
        if (idx < NTOT) {
            int b = idx / NROI;
            int n = idx % NROI;
            const float* reg = regcls + (size_t)b * 5 * NROI;
            float r0 = reg[n];
            float r1 = reg[NROI + n];
            float r2 = reg[2 * NROI + n];
            float r3 = reg[3 * NROI + n];
            float w = wan[n], h = han[n], xa = xan[n], ya = yan[n];
            float wreg = expf(r2) * w;
            float hreg = expf(r3) * h;
            float xreg = r0 * w + xa;
            float yreg = r1 * h + ya;
            float xis = xreg - wreg * 0.5f;
            float yis = yreg - hreg * 0.5f;
            float xfs = xreg + wreg * 0.5f;
            float yfs = yreg + hreg * 0.5f;
            float c0 = floorf(fmaxf(xis, 0.f));
            float c1 = floorf(fmaxf(yis, 0.f));
            float c2 = fminf(ceilf(xfs), 295.f);
            float c3 = fmaxf(ceilf(yfs), 295.f);   // (sic) max, as in source
            bool on = (xis < 296.f) && (yis < 296.f) && (xfs >= 0.f) && (yfs >= 0.f);
#define CONV_STEP(L) { c0 = fmaxf(c0 - 1.f, 0.f); c1 = fmaxf(c1 - 1.f, 0.f); \
                       c2 = fminf(c2, (float)(L)); c3 = fminf(c3, (float)(L)); }
#define MP_STEP()    { c0 = floorf(c0 * 0.5f); c1 = floorf(c1 * 0.5f); \
                       c2 = floorf(c2 * 0.5f); c3 = floorf(c3 * 0.5f); }
            CONV_STEP(293); CONV_STEP(291); MP_STEP();
            CONV_STEP(143); CONV_STEP(141); MP_STEP();
            CONV_STEP(68);  CONV_STEP(66);  CONV_STEP(64); MP_STEP();
            CONV_STEP(29);  CONV_STEP(27);  CONV_STEP(25); MP_STEP();
            CONV_STEP(10);  CONV_STEP(8);   CONV_STEP(6);
#undef CONV_STEP
#undef MP_STEP
            int xi = (int)c0, yi = (int)c1, xf = (int)c2, yf = (int)c3;
            int wx = xf + 1 - xi, wy = yf + 1 - yi;
            int kid;
            if (!on || wx <= 0 || wy <= 0 || xi > 6 || yi > 6 || xf < 0 || yf < 0) kid = 2401;
            else kid = ((xi * 7 + yi) * 7 + xf) * 7 + yf;
            int e = b * NKEY + kid;
            s_key[idx] = e;
            s_used[e] = 1;
        }
    }
    __syncthreads();
    // scan: 5 slots per thread
    int base = tid * 5;
    int loc[5];
    int cnt = 0;
#pragma unroll
    for (int u = 0; u < 5; u++) {
        int e = base + u;
        int v = (e < TOTKEY) ? s_used[e] : 0;
        loc[u] = v;
        cnt += v;
    }
    int lane = tid & 31, wid = tid >> 5;
    int x = cnt;
    for (int d = 1; d < 32; d <<= 1) {
        int y = __shfl_up_sync(0xffffffffu, x, d);
        if (lane >= d) x += y;
    }
    if (lane == 31) wsum[wid] = x;
    __syncthreads();
    if (wid == 0) {
        int w = wsum[lane];
        for (int d = 1; d < 32; d <<= 1) {
            int y = __shfl_up_sync(0xffffffffu, w, d);
            if (lane >= d) w += y;
        }
        wsum[lane] = w;
    }
    __syncthreads();
    int off = x - cnt + (wid ? wsum[wid - 1] : 0);
#pragma unroll
    for (int u = 0; u < 5; u++) {
        int e = base + u;
        if (e < TOTKEY) {
            if (loc[u]) {
                s_used[e] = off;        // in-place: used -> rowOf
                g_keyOfRow[off] = e;
                off++;
            } else {
                s_used[e] = -1;
            }
        }
    }
    if (tid == 1023) g_M[0] = off;
    __syncthreads();
#pragma unroll
    for (int u = 0; u < 2; u++) {
        int idx = tid + u * 1024;
        if (idx < NTOT) g_roiRow[idx] = s_used[s_key[idx]];
    }
}

// ---------------- kernel: pool (reads tf32-rounded features -> g_A is tf32-exact) ----------------
__global__ void pool_kernel() {
    int r = blockIdx.x;
    if (r >= g_M[0]) return;
    int e = g_keyOfRow[r];
    int b = e / NKEY;
    int kid = e % NKEY;
    float* Arow = g_A + (size_t)r * DD;
    if (kid == 2401) {
        for (int k = threadIdx.x; k < DD; k += 256) Arow[k] = 0.f;
        return;
    }
    int yf = kid % 7;
    int xf = (kid / 7) % 7;
    int yi = (kid / 49) % 7;
    int xi = kid / 343;
    int wx = xf + 1 - xi, wy = yf + 1 - yi;
    int bx[8], by[8];
#pragma unroll
    for (int ii = 0; ii < 8; ii++) {
        bx[ii] = xi + (ii * wx) / 7;
        by[ii] = yi + (ii * wy) / 7;
    }
    for (int c = threadIdx.x; c < CC; c += 256) {
        const float* f = g_F + ((size_t)b * CC + c) * 49;
        float v[49];
#pragma unroll
        for (int p = 0; p < 49; p++) v[p] = f[p];
#pragma unroll
        for (int i = 0; i < 7; i++) {
            int x0 = bx[i], x1 = bx[i + 1];
#pragma unroll
            for (int j = 0; j < 7; j++) {
                int y0 = by[j], y1 = by[j + 1];
                float m = -3.0e38f;
                for (int xx = x0; xx < x1; xx++)
                    for (int yy = y0; yy < y1; yy++)
                        m = fmaxf(m, v[xx * 7 + yy]);
                Arow[c * 49 + i * 7 + j] = (x1 > x0 && y1 > y0) ? m : 0.f;
            }
        }
    }
}

// ---------------- kernel: split-K tf32 GEMM, M-tile 128, 512 thr, 4Mx4N warps ----------------
#define GM_BM 128
#define SASTR 36
__global__ void __launch_bounds__(512) gemm_tc_kernel() {
    const int M = g_M[0];
    const int mBase = blockIdx.y * GM_BM;
    if (mBase >= M) return;
    const int k0 = blockIdx.x * KCHUNK;
    __shared__ __align__(16) float sA[GM_BM * SASTR];
    __shared__ __align__(16) float sW[H1 * SASTR];
    const int tid = threadIdx.x;
    const int lane = tid & 31, wid = tid >> 5;
    const int warpM = wid & 3;        // 32 rows each
    const int warpN = wid >> 2;       // nf groups: 7,6,6,6
    const int nfBase = (warpN == 0) ? 0 : 1 + warpN * 6;
    const int nfCnt = (warpN == 0) ? 7 : 6;

    float acc[2][7][4];
#pragma unroll
    for (int f = 0; f < 2; f++)
#pragma unroll
        for (int i = 0; i < 7; i++)
#pragma unroll
            for (int j = 0; j < 4; j++) acc[f][i][j] = 0.f;

    for (int slab = 0; slab < 16; slab++) {
        __syncthreads();
        // stage A: 128 rows x 32 k = 1024 float4 (already tf32-rounded)
#pragma unroll
        for (int u = 0; u < 2; u++) {
            int idx = tid + u * 512;
            int r = idx >> 3, kq = idx & 7;
            int g = mBase + r;
            float4 v = make_float4(0.f, 0.f, 0.f, 0.f);
            if (g < M)
                v = *reinterpret_cast<const float4*>(&g_A[(size_t)g * DD + k0 + slab * 32 + kq * 4]);
            *reinterpret_cast<float4*>(&sA[r * SASTR + kq * 4]) = v;
        }
        // stage W: 200 rows x 32 k = 1600 float4 (already tf32-rounded)
        for (int idx = tid; idx < H1 * 8; idx += 512) {
            int n = idx >> 3, kq = idx & 7;
            float4 v = *reinterpret_cast<const float4*>(&g_W[(size_t)n * DD + k0 + slab * 32 + kq * 4]);
            *reinterpret_cast<float4*>(&sW[n * SASTR + kq * 4]) = v;
        }
        __syncthreads();
#pragma unroll
        for (int ks = 0; ks < 4; ks++) {
            int kcol = ks * 8 + (lane & 3);
            int row0 = warpM * 32 + (lane >> 2);
            uint32_t a00 = __float_as_uint(sA[row0 * SASTR + kcol]);
            uint32_t a01 = __float_as_uint(sA[(row0 + 8) * SASTR + kcol]);
            uint32_t a02 = __float_as_uint(sA[row0 * SASTR + kcol + 4]);
            uint32_t a03 = __float_as_uint(sA[(row0 + 8) * SASTR + kcol + 4]);
            uint32_t a10 = __float_as_uint(sA[(row0 + 16) * SASTR + kcol]);
            uint32_t a11 = __float_as_uint(sA[(row0 + 24) * SASTR + kcol]);
            uint32_t a12 = __float_as_uint(sA[(row0 + 16) * SASTR + kcol + 4]);
            uint32_t a13 = __float_as_uint(sA[(row0 + 24) * SASTR + kcol + 4]);
#pragma unroll
            for (int nf = 0; nf < 7; nf++) {
                if (nf < nfCnt) {
                    int n0 = (nfBase + nf) * 8 + (lane >> 2);
                    uint32_t b0 = __float_as_uint(sW[n0 * SASTR + kcol]);
                    uint32_t b1 = __float_as_uint(sW[n0 * SASTR + kcol + 4]);
                    mma_tf32(acc[0][nf][0], acc[0][nf][1], acc[0][nf][2], acc[0][nf][3],
                             a00, a01, a02, a03, b0, b1);
                    mma_tf32(acc[1][nf][0], acc[1][nf][1], acc[1][nf][2], acc[1][nf][3],
                             a10, a11, a12, a13, b0, b1);
                }
            }
        }
    }
    // epilogue: partials to g_P
#pragma unroll
    for (int f = 0; f < 2; f++) {
        int rowA = mBase + warpM * 32 + f * 16 + (lane >> 2);
        int rowB = rowA + 8;
#pragma unroll
        for (int nf = 0; nf < 7; nf++) {
            if (nf < nfCnt) {
                int col = (nfBase + nf) * 8 + (lane & 3) * 2;
                if (rowA < MAXROWS)
                    *reinterpret_cast<float2*>(&g_P[((size_t)blockIdx.x * MAXROWS + rowA) * H1 + col]) =
                        make_float2(acc[f][nf][0], acc[f][nf][1]);
                if (rowB < MAXROWS)
                    *reinterpret_cast<float2*>(&g_P[((size_t)blockIdx.x * MAXROWS + rowB) * H1 + col]) =
                        make_float2(acc[f][nf][2], acc[f][nf][3]);
            }
        }
    }
}

// ---------------- kernel: fused split-K reduce + bias/relu + MLP tail ----------------
__device__ float g_out85[MAXROWS * 85];
__global__ void __launch_bounds__(256) mlp_kernel(const float* __restrict__ b1,
                                                  const float* __restrict__ w2, const float* __restrict__ b2,
                                                  const float* __restrict__ w3, const float* __restrict__ b3,
                                                  const float* __restrict__ w4, const float* __restrict__ b4) {
    int r = blockIdx.x;
    if (r >= g_M[0]) return;
    __shared__ float h1s[H1];
    __shared__ float h2s[H2];
    int t = threadIdx.x;
    if (t < H1) {
        float s = b1[t];
#pragma unroll
        for (int ks = 0; ks < KSPLIT; ks++)
            s += g_P[((size_t)ks * MAXROWS + r) * H1 + t];
        h1s[t] = fmaxf(s, 0.f);
    }
    __syncthreads();
    if (t < H2) {
        float s = b2[t];
        const float* wr = w2 + t * H1;
#pragma unroll 4
        for (int k = 0; k < H1; k++) s += h1s[k] * wr[k];
        h2s[t] = fmaxf(s, 0.f);
    }
    __syncthreads();
    if (t < 85) {
        float s;
        const float* wr;
        if (t < KC) { s = b3[t];      wr = w3 + t * H2; }
        else        { s = b4[t - KC]; wr = w4 + (t - KC) * H2; }
#pragma unroll 4
        for (int k = 0; k < H2; k++) s += h2s[k] * wr[k];
        g_out85[r * 85 + t] = s;
    }
}

// ---------------- kernel: scatter ----------------
__global__ void scatter_kernel(float* __restrict__ out) {
    int idx = blockIdx.x * blockDim.x + threadIdx.x;
    if (idx >= NTOT * 85) return;
    int bn = idx / 85;
    int q = idx % 85;
    int r = g_roiRow[bn];
    float val = g_out85[r * 85 + q];
    if (q < KC) {
        out[bn * KC + q] = val;                                        // z1: (B,A,G,G,17)
    } else {
        int k = (q - KC) / KC, cls = (q - KC) % KC;
        int b = bn / NROI, n = bn % NROI;
        out[NTOT * KC + (((b * 4 + k) * NROI + n) * KC + cls)] = val;  // z3: (B,4,A,G,G,17)
    }
}

// ---------------- launch ----------------
extern "C" void kernel_launch(void* const* d_in, const int* in_sizes, int n_in,
                              void* d_out, int out_size) {
    const float* cfeats = (const float*)d_in[0];
    const float* regcls = (const float*)d_in[1];
    const float* wan    = (const float*)d_in[2];
    const float* han    = (const float*)d_in[3];
    const float* xan    = (const float*)d_in[4];
    const float* yan    = (const float*)d_in[5];
    const float* w1     = (const float*)d_in[6];
    const float* b1     = (const float*)d_in[7];
    const float* w2     = (const float*)d_in[8];
    const float* b2     = (const float*)d_in[9];
    const float* w3     = (const float*)d_in[10];
    const float* b3     = (const float*)d_in[11];
    const float* w4     = (const float*)d_in[12];
    const float* b4     = (const float*)d_in[13];
    float* out = (float*)d_out;

    fused0_kernel<<<1 + NPREP, 1024>>>(regcls, wan, han, xan, yan, w1, cfeats);
    pool_kernel<<<MAXROWS, 256>>>();
    {
        dim3 grid(KSPLIT, (MAXROWS + GM_BM - 1) / GM_BM);
        gemm_tc_kernel<<<grid, 512>>>();
    }
    mlp_kernel<<<MAXROWS, 256>>>(b1, w2, b2, w3, b3, w4, b4);
    scatter_kernel<<<(NTOT * 85 + 255) / 256, 256>>>(out);
}

// round 5
// speedup vs baseline: 1.0298x; 1.0298x over previous
#include <cuda_runtime.h>
#include <cuda_bf16.h>
#include <math.h>
#include <stdint.h>

#define BB 2
#define NROI 625
#define NTOT 1250
#define CC 512
#define DD 25088            // 512*49
#define H1 200
#define H2 100
#define KC 17
#define NKEY 2402
#define TOTKEY 4804
#define MAXROWS 1250
#define KSPLIT 49
#define KCHUNK 512

// ---------------- scratch ----------------
__device__ float g_A[(size_t)MAXROWS * DD];
__device__ float g_P[(size_t)KSPLIT * MAXROWS * H1];
__device__ float g_W[(size_t)H1 * DD];     // tf32-rounded w1
__device__ float g_F[BB * CC * 49];        // tf32-rounded cfeats
__device__ float g_out85[MAXROWS * 85];
__device__ int   g_keyOfRow[TOTKEY];
__device__ int   g_roiRow[NTOT];
__device__ int   g_M[1];

// ---------------- tf32 helpers ----------------
__device__ __forceinline__ float tf32r(float x) {
    uint32_t u;
    asm("cvt.rna.tf32.f32 %0, %1;" : "=r"(u) : "f"(x));
    return __uint_as_float(u);
}
__device__ __forceinline__ void cvt4(float4& v) {
    v.x = tf32r(v.x); v.y = tf32r(v.y); v.z = tf32r(v.z); v.w = tf32r(v.w);
}
__device__ __forceinline__ void mma_tf32(float& d0, float& d1, float& d2, float& d3,
                                         uint32_t a0, uint32_t a1, uint32_t a2, uint32_t a3,
                                         uint32_t b0, uint32_t b1) {
    asm volatile(
        "mma.sync.aligned.m16n8k8.row.col.f32.tf32.tf32.f32 "
        "{%0,%1,%2,%3}, {%4,%5,%6,%7}, {%8,%9}, {%0,%1,%2,%3};\n"
        : "+f"(d0), "+f"(d1), "+f"(d2), "+f"(d3)
        : "r"(a0), "r"(a1), "r"(a2), "r"(a3), "r"(b0), "r"(b1));
}

// ---------------- kernel 0: control (1 block): boxes + dedup + scan + g_F cvt ----------------
__global__ void __launch_bounds__(1024) fused0_kernel(const float* __restrict__ regcls,
                                                      const float* __restrict__ wan,
                                                      const float* __restrict__ han,
                                                      const float* __restrict__ xan,
                                                      const float* __restrict__ yan,
                                                      const float* __restrict__ cf) {
    const int tid = threadIdx.x;
    // g_F: tf32-round features (12544 float4)
    {
        const int NF4 = BB * CC * 49 / 4;
        for (int i = tid; i < NF4; i += 1024) {
            float4 v = reinterpret_cast<const float4*>(cf)[i];
            cvt4(v);
            reinterpret_cast<float4*>(g_F)[i] = v;
        }
    }
    __shared__ int s_used[TOTKEY];
    __shared__ int s_key[NTOT];
    __shared__ int wsum[32];
    for (int i = tid; i < TOTKEY; i += 1024) s_used[i] = 0;
    __syncthreads();
#pragma unroll
    for (int u = 0; u < 2; u++) {
        int idx = tid + u * 1024;
        if (idx < NTOT) {
            int b = idx / NROI;
            int n = idx % NROI;
            const float* reg = regcls + (size_t)b * 5 * NROI;
            float r0 = reg[n];
            float r1 = reg[NROI + n];
            float r2 = reg[2 * NROI + n];
            float r3 = reg[3 * NROI + n];
            float w = wan[n], h = han[n], xa = xan[n], ya = yan[n];
            float wreg = expf(r2) * w;
            float hreg = expf(r3) * h;
            float xreg = r0 * w + xa;
            float yreg = r1 * h + ya;
            float xis = xreg - wreg * 0.5f;
            float yis = yreg - hreg * 0.5f;
            float xfs = xreg + wreg * 0.5f;
            float yfs = yreg + hreg * 0.5f;
            float c0 = floorf(fmaxf(xis, 0.f));
            float c1 = floorf(fmaxf(yis, 0.f));
            float c2 = fminf(ceilf(xfs), 295.f);
            float c3 = fmaxf(ceilf(yfs), 295.f);   // (sic) max, as in source
            bool on = (xis < 296.f) && (yis < 296.f) && (xfs >= 0.f) && (yfs >= 0.f);
#define CONV_STEP(L) { c0 = fmaxf(c0 - 1.f, 0.f); c1 = fmaxf(c1 - 1.f, 0.f); \
                       c2 = fminf(c2, (float)(L)); c3 = fminf(c3, (float)(L)); }
#define MP_STEP()    { c0 = floorf(c0 * 0.5f); c1 = floorf(c1 * 0.5f); \
                       c2 = floorf(c2 * 0.5f); c3 = floorf(c3 * 0.5f); }
            CONV_STEP(293); CONV_STEP(291); MP_STEP();
            CONV_STEP(143); CONV_STEP(141); MP_STEP();
            CONV_STEP(68);  CONV_STEP(66);  CONV_STEP(64); MP_STEP();
            CONV_STEP(29);  CONV_STEP(27);  CONV_STEP(25); MP_STEP();
            CONV_STEP(10);  CONV_STEP(8);   CONV_STEP(6);
#undef CONV_STEP
#undef MP_STEP
            int xi = (int)c0, yi = (int)c1, xf = (int)c2, yf = (int)c3;
            int wx = xf + 1 - xi, wy = yf + 1 - yi;
            int kid;
            if (!on || wx <= 0 || wy <= 0 || xi > 6 || yi > 6 || xf < 0 || yf < 0) kid = 2401;
            else kid = ((xi * 7 + yi) * 7 + xf) * 7 + yf;
            int e = b * NKEY + kid;
            s_key[idx] = e;
            s_used[e] = 1;
        }
    }
    __syncthreads();
    int base = tid * 5;
    int loc[5];
    int cnt = 0;
#pragma unroll
    for (int u = 0; u < 5; u++) {
        int e = base + u;
        int v = (e < TOTKEY) ? s_used[e] : 0;
        loc[u] = v;
        cnt += v;
    }
    int lane = tid & 31, wid = tid >> 5;
    int x = cnt;
    for (int d = 1; d < 32; d <<= 1) {
        int y = __shfl_up_sync(0xffffffffu, x, d);
        if (lane >= d) x += y;
    }
    if (lane == 31) wsum[wid] = x;
    __syncthreads();
    if (wid == 0) {
        int w = wsum[lane];
        for (int d = 1; d < 32; d <<= 1) {
            int y = __shfl_up_sync(0xffffffffu, w, d);
            if (lane >= d) w += y;
        }
        wsum[lane] = w;
    }
    __syncthreads();
    int off = x - cnt + (wid ? wsum[wid - 1] : 0);
#pragma unroll
    for (int u = 0; u < 5; u++) {
        int e = base + u;
        if (e < TOTKEY) {
            if (loc[u]) {
                s_used[e] = off;
                g_keyOfRow[off] = e;
                off++;
            } else {
                s_used[e] = -1;
            }
        }
    }
    if (tid == 1023) g_M[0] = off;
    __syncthreads();
#pragma unroll
    for (int u = 0; u < 2; u++) {
        int idx = tid + u * 1024;
        if (idx < NTOT) g_roiRow[idx] = s_used[s_key[idx]];
    }
}

// ---------------- kernel 1: pool (rows < M) + w1 tf32 prep (all blocks) ----------------
__global__ void __launch_bounds__(256) pool_prep_kernel(const float* __restrict__ w1) {
    const int r = blockIdx.x;   // 0..MAXROWS-1
    const int tid = threadIdx.x;
    // --- every block converts its static 1/MAXROWS slice of w1 ---
    {
        const size_t NW4 = (size_t)H1 * DD / 4;  // 1,254,400 float4
        for (size_t i = (size_t)r * 256 + tid; i < NW4; i += (size_t)MAXROWS * 256) {
            float4 v = reinterpret_cast<const float4*>(w1)[i];
            cvt4(v);
            reinterpret_cast<float4*>(g_W)[i] = v;
        }
    }
    const int M = g_M[0];
    if (r >= M) return;
    int e = g_keyOfRow[r];
    int b = e / NKEY;
    int kid = e % NKEY;
    float* Arow = g_A + (size_t)r * DD;
    if (kid == 2401) {
        for (int k = tid; k < DD; k += 256) Arow[k] = 0.f;
        return;
    }
    int yf = kid % 7;
    int xf = (kid / 7) % 7;
    int yi = (kid / 49) % 7;
    int xi = kid / 343;
    int wx = xf + 1 - xi, wy = yf + 1 - yi;
    int bx[8], by[8];
#pragma unroll
    for (int ii = 0; ii < 8; ii++) {
        bx[ii] = xi + (ii * wx) / 7;
        by[ii] = yi + (ii * wy) / 7;
    }
    for (int c = tid; c < CC; c += 256) {
        const float* f = g_F + ((size_t)b * CC + c) * 49;
        float v[49];
#pragma unroll
        for (int p = 0; p < 49; p++) v[p] = f[p];
#pragma unroll
        for (int i = 0; i < 7; i++) {
            int x0 = bx[i], x1 = bx[i + 1];
#pragma unroll
            for (int j = 0; j < 7; j++) {
                int y0 = by[j], y1 = by[j + 1];
                float m = -3.0e38f;
                for (int xx = x0; xx < x1; xx++)
                    for (int yy = y0; yy < y1; yy++)
                        m = fmaxf(m, v[xx * 7 + yy]);
                Arow[c * 49 + i * 7 + j] = (x1 > x0 && y1 > y0) ? m : 0.f;
            }
        }
    }
}

// ---------------- kernel 2: split-K tf32 GEMM, M-tile 128, 512 thr, 4Mx4N warps ----------------
#define GM_BM 128
#define SASTR 36
__global__ void __launch_bounds__(512) gemm_tc_kernel() {
    const int M = g_M[0];
    const int mBase = blockIdx.y * GM_BM;
    if (mBase >= M) return;
    const int k0 = blockIdx.x * KCHUNK;
    __shared__ __align__(16) float sA[GM_BM * SASTR];
    __shared__ __align__(16) float sW[H1 * SASTR];
    const int tid = threadIdx.x;
    const int lane = tid & 31, wid = tid >> 5;
    const int warpM = wid & 3;
    const int warpN = wid >> 2;
    const int nfBase = (warpN == 0) ? 0 : 1 + warpN * 6;
    const int nfCnt = (warpN == 0) ? 7 : 6;

    float acc[2][7][4];
#pragma unroll
    for (int f = 0; f < 2; f++)
#pragma unroll
        for (int i = 0; i < 7; i++)
#pragma unroll
            for (int j = 0; j < 4; j++) acc[f][i][j] = 0.f;

    for (int slab = 0; slab < 16; slab++) {
        __syncthreads();
#pragma unroll
        for (int u = 0; u < 2; u++) {
            int idx = tid + u * 512;
            int rr = idx >> 3, kq = idx & 7;
            int g = mBase + rr;
            float4 v = make_float4(0.f, 0.f, 0.f, 0.f);
            if (g < M)
                v = *reinterpret_cast<const float4*>(&g_A[(size_t)g * DD + k0 + slab * 32 + kq * 4]);
            *reinterpret_cast<float4*>(&sA[rr * SASTR + kq * 4]) = v;
        }
        for (int idx = tid; idx < H1 * 8; idx += 512) {
            int n = idx >> 3, kq = idx & 7;
            float4 v = *reinterpret_cast<const float4*>(&g_W[(size_t)n * DD + k0 + slab * 32 + kq * 4]);
            *reinterpret_cast<float4*>(&sW[n * SASTR + kq * 4]) = v;
        }
        __syncthreads();
#pragma unroll
        for (int ks = 0; ks < 4; ks++) {
            int kcol = ks * 8 + (lane & 3);
            int row0 = warpM * 32 + (lane >> 2);
            uint32_t a00 = __float_as_uint(sA[row0 * SASTR + kcol]);
            uint32_t a01 = __float_as_uint(sA[(row0 + 8) * SASTR + kcol]);
            uint32_t a02 = __float_as_uint(sA[row0 * SASTR + kcol + 4]);
            uint32_t a03 = __float_as_uint(sA[(row0 + 8) * SASTR + kcol + 4]);
            uint32_t a10 = __float_as_uint(sA[(row0 + 16) * SASTR + kcol]);
            uint32_t a11 = __float_as_uint(sA[(row0 + 24) * SASTR + kcol]);
            uint32_t a12 = __float_as_uint(sA[(row0 + 16) * SASTR + kcol + 4]);
            uint32_t a13 = __float_as_uint(sA[(row0 + 24) * SASTR + kcol + 4]);
#pragma unroll
            for (int nf = 0; nf < 7; nf++) {
                if (nf < nfCnt) {
                    int n0 = (nfBase + nf) * 8 + (lane >> 2);
                    uint32_t b0 = __float_as_uint(sW[n0 * SASTR + kcol]);
                    uint32_t b1 = __float_as_uint(sW[n0 * SASTR + kcol + 4]);
                    mma_tf32(acc[0][nf][0], acc[0][nf][1], acc[0][nf][2], acc[0][nf][3],
                             a00, a01, a02, a03, b0, b1);
                    mma_tf32(acc[1][nf][0], acc[1][nf][1], acc[1][nf][2], acc[1][nf][3],
                             a10, a11, a12, a13, b0, b1);
                }
            }
        }
    }
#pragma unroll
    for (int f = 0; f < 2; f++) {
        int rowA = mBase + warpM * 32 + f * 16 + (lane >> 2);
        int rowB = rowA + 8;
#pragma unroll
        for (int nf = 0; nf < 7; nf++) {
            if (nf < nfCnt) {
                int col = (nfBase + nf) * 8 + (lane & 3) * 2;
                if (rowA < MAXROWS)
                    *reinterpret_cast<float2*>(&g_P[((size_t)blockIdx.x * MAXROWS + rowA) * H1 + col]) =
                        make_float2(acc[f][nf][0], acc[f][nf][1]);
                if (rowB < MAXROWS)
                    *reinterpret_cast<float2*>(&g_P[((size_t)blockIdx.x * MAXROWS + rowB) * H1 + col]) =
                        make_float2(acc[f][nf][2], acc[f][nf][3]);
            }
        }
    }
}

// ---------------- kernel 3: fused reduce + MLP (warp-cooperative, coalesced) ----------------
__global__ void __launch_bounds__(256) mlp_kernel(const float* __restrict__ b1,
                                                  const float* __restrict__ w2, const float* __restrict__ b2,
                                                  const float* __restrict__ w3, const float* __restrict__ b3,
                                                  const float* __restrict__ w4, const float* __restrict__ b4) {
    int r = blockIdx.x;
    if (r >= g_M[0]) return;
    __shared__ float h1s[H1];
    __shared__ float h2s[H2];
    const int t = threadIdx.x;
    const int lane = t & 31, wid = t >> 5;
    // split-K reduce + bias + relu (coalesced across t)
    if (t < H1) {
        float s = b1[t];
#pragma unroll
        for (int ks = 0; ks < KSPLIT; ks++)
            s += g_P[((size_t)ks * MAXROWS + r) * H1 + t];
        h1s[t] = fmaxf(s, 0.f);
    }
    __syncthreads();
    // h2: warp per output, lanes over k (coalesced w2 reads)
    for (int j = wid; j < H2; j += 8) {
        const float* wr = w2 + j * H1;
        float s = 0.f;
#pragma unroll
        for (int k = lane; k < H1; k += 32) s += wr[k] * h1s[k];
#pragma unroll
        for (int d = 16; d > 0; d >>= 1) s += __shfl_xor_sync(0xffffffffu, s, d);
        if (lane == 0) h2s[j] = fmaxf(s + b2[j], 0.f);
    }
    __syncthreads();
    // out85: warp per output
    for (int q = wid; q < 85; q += 8) {
        const float* wr;
        float bias;
        if (q < KC) { wr = w3 + q * H2;        bias = b3[q]; }
        else        { wr = w4 + (q - KC) * H2; bias = b4[q - KC]; }
        float s = 0.f;
#pragma unroll
        for (int k = lane; k < H2; k += 32) s += wr[k] * h2s[k];
#pragma unroll
        for (int d = 16; d > 0; d >>= 1) s += __shfl_xor_sync(0xffffffffu, s, d);
        if (lane == 0) g_out85[r * 85 + q] = s + bias;
    }
}

// ---------------- kernel 4: scatter ----------------
__global__ void scatter_kernel(float* __restrict__ out) {
    int idx = blockIdx.x * blockDim.x + threadIdx.x;
    if (idx >= NTOT * 85) return;
    int bn = idx / 85;
    int q = idx % 85;
    int r = g_roiRow[bn];
    float val = g_out85[r * 85 + q];
    if (q < KC) {
        out[bn * KC + q] = val;                                        // z1
    } else {
        int k = (q - KC) / KC, cls = (q - KC) % KC;
        int b = bn / NROI, n = bn % NROI;
        out[NTOT * KC + (((b * 4 + k) * NROI + n) * KC + cls)] = val;  // z3
    }
}

// ---------------- launch ----------------
extern "C" void kernel_launch(void* const* d_in, const int* in_sizes, int n_in,
                              void* d_out, int out_size) {
    const float* cfeats = (const float*)d_in[0];
    const float* regcls = (const float*)d_in[1];
    const float* wan    = (const float*)d_in[2];
    const float* han    = (const float*)d_in[3];
    const float* xan    = (const float*)d_in[4];
    const float* yan    = (const float*)d_in[5];
    const float* w1     = (const float*)d_in[6];
    const float* b1     = (const float*)d_in[7];
    const float* w2     = (const float*)d_in[8];
    const float* b2     = (const float*)d_in[9];
    const float* w3     = (const float*)d_in[10];
    const float* b3     = (const float*)d_in[11];
    const float* w4     = (const float*)d_in[12];
    const float* b4     = (const float*)d_in[13];
    float* out = (float*)d_out;

    fused0_kernel<<<1, 1024>>>(regcls, wan, han, xan, yan, cfeats);
    pool_prep_kernel<<<MAXROWS, 256>>>(w1);
    {
        dim3 grid(KSPLIT, (MAXROWS + GM_BM - 1) / GM_BM);
        gemm_tc_kernel<<<grid, 512>>>();
    }
    mlp_kernel<<<MAXROWS, 256>>>(b1, w2, b2, w3, b3, w4, b4);
    scatter_kernel<<<(NTOT * 85 + 255) / 256, 256>>>(out);
}

// round 6
// speedup vs baseline: 1.1676x; 1.1338x over previous
#include <cuda_runtime.h>
#include <cuda_bf16.h>
#include <math.h>
#include <stdint.h>

#define BB 2
#define NROI 625
#define NTOT 1250
#define CC 512
#define DD 25088            // 512*49
#define H1 200
#define H2 100
#define KC 17
#define NKEY 2402
#define TOTKEY 4804
#define MAXROWS 1250
#define KSPLIT 49
#define KCHUNK 512

// ---------------- scratch ----------------
__device__ float g_A[(size_t)MAXROWS * DD];
__device__ float g_P[(size_t)MAXROWS * KSPLIT * H1];   // [row][ks][H1]
__device__ float g_F[BB * CC * 49];        // tf32-rounded cfeats
__device__ float g_out85[MAXROWS * 85];
__device__ int   g_keyOfRow[TOTKEY];
__device__ int   g_roiRow[NTOT];
__device__ int   g_M[1];

// ---------------- tf32 helpers ----------------
__device__ __forceinline__ float tf32r(float x) {
    uint32_t u;
    asm("cvt.rna.tf32.f32 %0, %1;" : "=r"(u) : "f"(x));
    return __uint_as_float(u);
}
__device__ __forceinline__ void cvt4(float4& v) {
    v.x = tf32r(v.x); v.y = tf32r(v.y); v.z = tf32r(v.z); v.w = tf32r(v.w);
}
__device__ __forceinline__ void mma_tf32(float& d0, float& d1, float& d2, float& d3,
                                         uint32_t a0, uint32_t a1, uint32_t a2, uint32_t a3,
                                         uint32_t b0, uint32_t b1) {
    asm volatile(
        "mma.sync.aligned.m16n8k8.row.col.f32.tf32.tf32.f32 "
        "{%0,%1,%2,%3}, {%4,%5,%6,%7}, {%8,%9}, {%0,%1,%2,%3};\n"
        : "+f"(d0), "+f"(d1), "+f"(d2), "+f"(d3)
        : "r"(a0), "r"(a1), "r"(a2), "r"(a3), "r"(b0), "r"(b1));
}

// ---------------- kernel 0: control (1 block): boxes + dedup + scan + g_F cvt ----------------
__global__ void __launch_bounds__(1024) fused0_kernel(const float* __restrict__ regcls,
                                                      const float* __restrict__ wan,
                                                      const float* __restrict__ han,
                                                      const float* __restrict__ xan,
                                                      const float* __restrict__ yan,
                                                      const float* __restrict__ cf) {
    const int tid = threadIdx.x;
    {
        const int NF4 = BB * CC * 49 / 4;
        for (int i = tid; i < NF4; i += 1024) {
            float4 v = reinterpret_cast<const float4*>(cf)[i];
            cvt4(v);
            reinterpret_cast<float4*>(g_F)[i] = v;
        }
    }
    __shared__ int s_used[TOTKEY];
    __shared__ int s_key[NTOT];
    __shared__ int wsum[32];
    for (int i = tid; i < TOTKEY; i += 1024) s_used[i] = 0;
    __syncthreads();
#pragma unroll
    for (int u = 0; u < 2; u++) {
        int idx = tid + u * 1024;
        if (idx < NTOT) {
            int b = idx / NROI;
            int n = idx % NROI;
            const float* reg = regcls + (size_t)b * 5 * NROI;
            float r0 = reg[n];
            float r1 = reg[NROI + n];
            float r2 = reg[2 * NROI + n];
            float r3 = reg[3 * NROI + n];
            float w = wan[n], h = han[n], xa = xan[n], ya = yan[n];
            float wreg = expf(r2) * w;
            float hreg = expf(r3) * h;
            float xreg = r0 * w + xa;
            float yreg = r1 * h + ya;
            float xis = xreg - wreg * 0.5f;
            float yis = yreg - hreg * 0.5f;
            float xfs = xreg + wreg * 0.5f;
            float yfs = yreg + hreg * 0.5f;
            float c0 = floorf(fmaxf(xis, 0.f));
            float c1 = floorf(fmaxf(yis, 0.f));
            float c2 = fminf(ceilf(xfs), 295.f);
            float c3 = fmaxf(ceilf(yfs), 295.f);   // (sic) max, as in source
            bool on = (xis < 296.f) && (yis < 296.f) && (xfs >= 0.f) && (yfs >= 0.f);
#define CONV_STEP(L) { c0 = fmaxf(c0 - 1.f, 0.f); c1 = fmaxf(c1 - 1.f, 0.f); \
                       c2 = fminf(c2, (float)(L)); c3 = fminf(c3, (float)(L)); }
#define MP_STEP()    { c0 = floorf(c0 * 0.5f); c1 = floorf(c1 * 0.5f); \
                       c2 = floorf(c2 * 0.5f); c3 = floorf(c3 * 0.5f); }
            CONV_STEP(293); CONV_STEP(291); MP_STEP();
            CONV_STEP(143); CONV_STEP(141); MP_STEP();
            CONV_STEP(68);  CONV_STEP(66);  CONV_STEP(64); MP_STEP();
            CONV_STEP(29);  CONV_STEP(27);  CONV_STEP(25); MP_STEP();
            CONV_STEP(10);  CONV_STEP(8);   CONV_STEP(6);
#undef CONV_STEP
#undef MP_STEP
            int xi = (int)c0, yi = (int)c1, xf = (int)c2, yf = (int)c3;
            int wx = xf + 1 - xi, wy = yf + 1 - yi;
            int kid;
            if (!on || wx <= 0 || wy <= 0 || xi > 6 || yi > 6 || xf < 0 || yf < 0) kid = 2401;
            else kid = ((xi * 7 + yi) * 7 + xf) * 7 + yf;
            int e = b * NKEY + kid;
            s_key[idx] = e;
            s_used[e] = 1;
        }
    }
    __syncthreads();
    int base = tid * 5;
    int loc[5];
    int cnt = 0;
#pragma unroll
    for (int u = 0; u < 5; u++) {
        int e = base + u;
        int v = (e < TOTKEY) ? s_used[e] : 0;
        loc[u] = v;
        cnt += v;
    }
    int lane = tid & 31, wid = tid >> 5;
    int x = cnt;
    for (int d = 1; d < 32; d <<= 1) {
        int y = __shfl_up_sync(0xffffffffu, x, d);
        if (lane >= d) x += y;
    }
    if (lane == 31) wsum[wid] = x;
    __syncthreads();
    if (wid == 0) {
        int w = wsum[lane];
        for (int d = 1; d < 32; d <<= 1) {
            int y = __shfl_up_sync(0xffffffffu, w, d);
            if (lane >= d) w += y;
        }
        wsum[lane] = w;
    }
    __syncthreads();
    int off = x - cnt + (wid ? wsum[wid - 1] : 0);
#pragma unroll
    for (int u = 0; u < 5; u++) {
        int e = base + u;
        if (e < TOTKEY) {
            if (loc[u]) {
                s_used[e] = off;
                g_keyOfRow[off] = e;
                off++;
            } else {
                s_used[e] = -1;
            }
        }
    }
    if (tid == 1023) g_M[0] = off;
    __syncthreads();
#pragma unroll
    for (int u = 0; u < 2; u++) {
        int idx = tid + u * 1024;
        if (idx < NTOT) g_roiRow[idx] = s_used[s_key[idx]];
    }
}

// ---------------- kernel 1: pool ----------------
__global__ void __launch_bounds__(256) pool_kernel() {
    const int r = blockIdx.x;
    const int tid = threadIdx.x;
    const int M = g_M[0];
    if (r >= M) return;
    int e = g_keyOfRow[r];
    int b = e / NKEY;
    int kid = e % NKEY;
    float* Arow = g_A + (size_t)r * DD;
    if (kid == 2401) {
        for (int k = tid; k < DD; k += 256) Arow[k] = 0.f;
        return;
    }
    int yf = kid % 7;
    int xf = (kid / 7) % 7;
    int yi = (kid / 49) % 7;
    int xi = kid / 343;
    int wx = xf + 1 - xi, wy = yf + 1 - yi;
    int bx[8], by[8];
#pragma unroll
    for (int ii = 0; ii < 8; ii++) {
        bx[ii] = xi + (ii * wx) / 7;
        by[ii] = yi + (ii * wy) / 7;
    }
    for (int c = tid; c < CC; c += 256) {
        const float* f = g_F + ((size_t)b * CC + c) * 49;
        float v[49];
#pragma unroll
        for (int p = 0; p < 49; p++) v[p] = f[p];
#pragma unroll
        for (int i = 0; i < 7; i++) {
            int x0 = bx[i], x1 = bx[i + 1];
#pragma unroll
            for (int j = 0; j < 7; j++) {
                int y0 = by[j], y1 = by[j + 1];
                float m = -3.0e38f;
                for (int xx = x0; xx < x1; xx++)
                    for (int yy = y0; yy < y1; yy++)
                        m = fmaxf(m, v[xx * 7 + yy]);
                Arow[c * 49 + i * 7 + j] = (x1 > x0 && y1 > y0) ? m : 0.f;
            }
        }
    }
}

// ---------------- kernel 2: split-K tf32 GEMM, w1 fed raw (HW truncates) ----------------
#define GM_BM 128
#define SASTR 36
__global__ void __launch_bounds__(512) gemm_tc_kernel(const float* __restrict__ w1) {
    const int M = g_M[0];
    const int mBase = blockIdx.y * GM_BM;
    if (mBase >= M) return;
    const int k0 = blockIdx.x * KCHUNK;
    __shared__ __align__(16) float sA[GM_BM * SASTR];
    __shared__ __align__(16) float sW[H1 * SASTR];
    const int tid = threadIdx.x;
    const int lane = tid & 31, wid = tid >> 5;
    const int warpM = wid & 3;
    const int warpN = wid >> 2;
    const int nfBase = (warpN == 0) ? 0 : 1 + warpN * 6;
    const int nfCnt = (warpN == 0) ? 7 : 6;

    float acc[2][7][4];
#pragma unroll
    for (int f = 0; f < 2; f++)
#pragma unroll
        for (int i = 0; i < 7; i++)
#pragma unroll
            for (int j = 0; j < 4; j++) acc[f][i][j] = 0.f;

    for (int slab = 0; slab < 16; slab++) {
        __syncthreads();
#pragma unroll
        for (int u = 0; u < 2; u++) {
            int idx = tid + u * 512;
            int rr = idx >> 3, kq = idx & 7;
            int g = mBase + rr;
            float4 v = make_float4(0.f, 0.f, 0.f, 0.f);
            if (g < M)
                v = *reinterpret_cast<const float4*>(&g_A[(size_t)g * DD + k0 + slab * 32 + kq * 4]);
            *reinterpret_cast<float4*>(&sA[rr * SASTR + kq * 4]) = v;
        }
        for (int idx = tid; idx < H1 * 8; idx += 512) {
            int n = idx >> 3, kq = idx & 7;
            float4 v = *reinterpret_cast<const float4*>(&w1[(size_t)n * DD + k0 + slab * 32 + kq * 4]);
            *reinterpret_cast<float4*>(&sW[n * SASTR + kq * 4]) = v;   // raw fp32 bits; TC truncates
        }
        __syncthreads();
#pragma unroll
        for (int ks = 0; ks < 4; ks++) {
            int kcol = ks * 8 + (lane & 3);
            int row0 = warpM * 32 + (lane >> 2);
            uint32_t a00 = __float_as_uint(sA[row0 * SASTR + kcol]);
            uint32_t a01 = __float_as_uint(sA[(row0 + 8) * SASTR + kcol]);
            uint32_t a02 = __float_as_uint(sA[row0 * SASTR + kcol + 4]);
            uint32_t a03 = __float_as_uint(sA[(row0 + 8) * SASTR + kcol + 4]);
            uint32_t a10 = __float_as_uint(sA[(row0 + 16) * SASTR + kcol]);
            uint32_t a11 = __float_as_uint(sA[(row0 + 24) * SASTR + kcol]);
            uint32_t a12 = __float_as_uint(sA[(row0 + 16) * SASTR + kcol + 4]);
            uint32_t a13 = __float_as_uint(sA[(row0 + 24) * SASTR + kcol + 4]);
#pragma unroll
            for (int nf = 0; nf < 7; nf++) {
                if (nf < nfCnt) {
                    int n0 = (nfBase + nf) * 8 + (lane >> 2);
                    uint32_t b0 = __float_as_uint(sW[n0 * SASTR + kcol]);
                    uint32_t b1 = __float_as_uint(sW[n0 * SASTR + kcol + 4]);
                    mma_tf32(acc[0][nf][0], acc[0][nf][1], acc[0][nf][2], acc[0][nf][3],
                             a00, a01, a02, a03, b0, b1);
                    mma_tf32(acc[1][nf][0], acc[1][nf][1], acc[1][nf][2], acc[1][nf][3],
                             a10, a11, a12, a13, b0, b1);
                }
            }
        }
    }
#pragma unroll
    for (int f = 0; f < 2; f++) {
        int rowA = mBase + warpM * 32 + f * 16 + (lane >> 2);
        int rowB = rowA + 8;
#pragma unroll
        for (int nf = 0; nf < 7; nf++) {
            if (nf < nfCnt) {
                int col = (nfBase + nf) * 8 + (lane & 3) * 2;
                if (rowA < MAXROWS)
                    *reinterpret_cast<float2*>(&g_P[((size_t)rowA * KSPLIT + blockIdx.x) * H1 + col]) =
                        make_float2(acc[f][nf][0], acc[f][nf][1]);
                if (rowB < MAXROWS)
                    *reinterpret_cast<float2*>(&g_P[((size_t)rowB * KSPLIT + blockIdx.x) * H1 + col]) =
                        make_float2(acc[f][nf][2], acc[f][nf][3]);
            }
        }
    }
}

// ---------------- kernel 3: fused reduce + MLP (contiguous g_P reads) ----------------
__global__ void __launch_bounds__(256) mlp_kernel(const float* __restrict__ b1,
                                                  const float* __restrict__ w2, const float* __restrict__ b2,
                                                  const float* __restrict__ w3, const float* __restrict__ b3,
                                                  const float* __restrict__ w4, const float* __restrict__ b4) {
    int r = blockIdx.x;
    if (r >= g_M[0]) return;
    __shared__ float h1s[H1];
    __shared__ float h2s[H2];
    const int t = threadIdx.x;
    const int lane = t & 31, wid = t >> 5;
    // split-K reduce over contiguous [r][ks][H1] span (39 KB per row)
    {
        const float* Pr = g_P + (size_t)r * KSPLIT * H1;
        if (t < H1) {
            float s = b1[t];
#pragma unroll
            for (int ks = 0; ks < KSPLIT; ks++)
                s += Pr[ks * H1 + t];
            h1s[t] = fmaxf(s, 0.f);
        }
    }
    __syncthreads();
    for (int j = wid; j < H2; j += 8) {
        const float* wr = w2 + j * H1;
        float s = 0.f;
#pragma unroll
        for (int k = lane; k < H1; k += 32) s += wr[k] * h1s[k];
#pragma unroll
        for (int d = 16; d > 0; d >>= 1) s += __shfl_xor_sync(0xffffffffu, s, d);
        if (lane == 0) h2s[j] = fmaxf(s + b2[j], 0.f);
    }
    __syncthreads();
    for (int q = wid; q < 85; q += 8) {
        const float* wr;
        float bias;
        if (q < KC) { wr = w3 + q * H2;        bias = b3[q]; }
        else        { wr = w4 + (q - KC) * H2; bias = b4[q - KC]; }
        float s = 0.f;
#pragma unroll
        for (int k = lane; k < H2; k += 32) s += wr[k] * h2s[k];
#pragma unroll
        for (int d = 16; d > 0; d >>= 1) s += __shfl_xor_sync(0xffffffffu, s, d);
        if (lane == 0) g_out85[r * 85 + q] = s + bias;
    }
}

// ---------------- kernel 4: scatter ----------------
__global__ void scatter_kernel(float* __restrict__ out) {
    int idx = blockIdx.x * blockDim.x + threadIdx.x;
    if (idx >= NTOT * 85) return;
    int bn = idx / 85;
    int q = idx % 85;
    int r = g_roiRow[bn];
    float val = g_out85[r * 85 + q];
    if (q < KC) {
        out[bn * KC + q] = val;                                        // z1
    } else {
        int k = (q - KC) / KC, cls = (q - KC) % KC;
        int b = bn / NROI, n = bn % NROI;
        out[NTOT * KC + (((b * 4 + k) * NROI + n) * KC + cls)] = val;  // z3
    }
}

// ---------------- launch ----------------
extern "C" void kernel_launch(void* const* d_in, const int* in_sizes, int n_in,
                              void* d_out, int out_size) {
    const float* cfeats = (const float*)d_in[0];
    const float* regcls = (const float*)d_in[1];
    const float* wan    = (const float*)d_in[2];
    const float* han    = (const float*)d_in[3];
    const float* xan    = (const float*)d_in[4];
    const float* yan    = (const float*)d_in[5];
    const float* w1     = (const float*)d_in[6];
    const float* b1     = (const float*)d_in[7];
    const float* w2     = (const float*)d_in[8];
    const float* b2     = (const float*)d_in[9];
    const float* w3     = (const float*)d_in[10];
    const float* b3     = (const float*)d_in[11];
    const float* w4     = (const float*)d_in[12];
    const float* b4     = (const float*)d_in[13];
    float* out = (float*)d_out;

    fused0_kernel<<<1, 1024>>>(regcls, wan, han, xan, yan, cfeats);
    pool_kernel<<<MAXROWS, 256>>>();
    {
        dim3 grid(KSPLIT, (MAXROWS + GM_BM - 1) / GM_BM);
        gemm_tc_kernel<<<grid, 512>>>(w1);
    }
    mlp_kernel<<<MAXROWS, 256>>>(b1, w2, b2, w3, b3, w4, b4);
    scatter_kernel<<<(NTOT * 85 + 255) / 256, 256>>>(out);
}

// round 7
// speedup vs baseline: 1.4371x; 1.2309x over previous
#include <cuda_runtime.h>
#include <cuda_bf16.h>
#include <math.h>
#include <stdint.h>

#define BB 2
#define NROI 625
#define NTOT 1250
#define CC 512
#define DD 25088            // 512*49
#define H1 200
#define H2 100
#define KC 17
#define NKEY 2402
#define TOTKEY 4804
#define MAXROWS 1250
#define KSPLIT 49
#define KCHUNK 512

// ---------------- scratch ----------------
__device__ float g_A[(size_t)MAXROWS * DD];
__device__ float g_P[(size_t)MAXROWS * KSPLIT * H1];   // [row][ks][H1]
__device__ float g_F[BB * CC * 49];        // tf32-rounded cfeats
__device__ float g_out85[MAXROWS * 85];
__device__ int   g_keyOfRow[TOTKEY];
__device__ int   g_roiRow[NTOT];
__device__ int   g_M[1];

// ---------------- tf32 helpers ----------------
__device__ __forceinline__ float tf32r(float x) {
    uint32_t u;
    asm("cvt.rna.tf32.f32 %0, %1;" : "=r"(u) : "f"(x));
    return __uint_as_float(u);
}
__device__ __forceinline__ void cvt4(float4& v) {
    v.x = tf32r(v.x); v.y = tf32r(v.y); v.z = tf32r(v.z); v.w = tf32r(v.w);
}
__device__ __forceinline__ void mma_tf32(float& d0, float& d1, float& d2, float& d3,
                                         uint32_t a0, uint32_t a1, uint32_t a2, uint32_t a3,
                                         uint32_t b0, uint32_t b1) {
    asm volatile(
        "mma.sync.aligned.m16n8k8.row.col.f32.tf32.tf32.f32 "
        "{%0,%1,%2,%3}, {%4,%5,%6,%7}, {%8,%9}, {%0,%1,%2,%3};\n"
        : "+f"(d0), "+f"(d1), "+f"(d2), "+f"(d3)
        : "r"(a0), "r"(a1), "r"(a2), "r"(a3), "r"(b0), "r"(b1));
}

// ---------------- kernel 0: control (1 block): boxes + dedup + scan + g_F cvt ----------------
__global__ void __launch_bounds__(1024) fused0_kernel(const float* __restrict__ regcls,
                                                      const float* __restrict__ wan,
                                                      const float* __restrict__ han,
                                                      const float* __restrict__ xan,
                                                      const float* __restrict__ yan,
                                                      const float* __restrict__ cf) {
    const int tid = threadIdx.x;
    {
        const int NF4 = BB * CC * 49 / 4;
        for (int i = tid; i < NF4; i += 1024) {
            float4 v = reinterpret_cast<const float4*>(cf)[i];
            cvt4(v);
            reinterpret_cast<float4*>(g_F)[i] = v;
        }
    }
    __shared__ int s_used[TOTKEY];
    __shared__ int s_key[NTOT];
    __shared__ int wsum[32];
    for (int i = tid; i < TOTKEY; i += 1024) s_used[i] = 0;
    __syncthreads();
#pragma unroll
    for (int u = 0; u < 2; u++) {
        int idx = tid + u * 1024;
        if (idx < NTOT) {
            int b = idx / NROI;
            int n = idx % NROI;
            const float* reg = regcls + (size_t)b * 5 * NROI;
            float r0 = reg[n];
            float r1 = reg[NROI + n];
            float r2 = reg[2 * NROI + n];
            float r3 = reg[3 * NROI + n];
            float w = wan[n], h = han[n], xa = xan[n], ya = yan[n];
            float wreg = expf(r2) * w;
            float hreg = expf(r3) * h;
            float xreg = r0 * w + xa;
            float yreg = r1 * h + ya;
            float xis = xreg - wreg * 0.5f;
            float yis = yreg - hreg * 0.5f;
            float xfs = xreg + wreg * 0.5f;
            float yfs = yreg + hreg * 0.5f;
            float c0 = floorf(fmaxf(xis, 0.f));
            float c1 = floorf(fmaxf(yis, 0.f));
            float c2 = fminf(ceilf(xfs), 295.f);
            float c3 = fmaxf(ceilf(yfs), 295.f);   // (sic) max, as in source
            bool on = (xis < 296.f) && (yis < 296.f) && (xfs >= 0.f) && (yfs >= 0.f);
#define CONV_STEP(L) { c0 = fmaxf(c0 - 1.f, 0.f); c1 = fmaxf(c1 - 1.f, 0.f); \
                       c2 = fminf(c2, (float)(L)); c3 = fminf(c3, (float)(L)); }
#define MP_STEP()    { c0 = floorf(c0 * 0.5f); c1 = floorf(c1 * 0.5f); \
                       c2 = floorf(c2 * 0.5f); c3 = floorf(c3 * 0.5f); }
            CONV_STEP(293); CONV_STEP(291); MP_STEP();
            CONV_STEP(143); CONV_STEP(141); MP_STEP();
            CONV_STEP(68);  CONV_STEP(66);  CONV_STEP(64); MP_STEP();
            CONV_STEP(29);  CONV_STEP(27);  CONV_STEP(25); MP_STEP();
            CONV_STEP(10);  CONV_STEP(8);   CONV_STEP(6);
#undef CONV_STEP
#undef MP_STEP
            int xi = (int)c0, yi = (int)c1, xf = (int)c2, yf = (int)c3;
            int wx = xf + 1 - xi, wy = yf + 1 - yi;
            int kid;
            if (!on || wx <= 0 || wy <= 0 || xi > 6 || yi > 6 || xf < 0 || yf < 0) kid = 2401;
            else kid = ((xi * 7 + yi) * 7 + xf) * 7 + yf;
            int e = b * NKEY + kid;
            s_key[idx] = e;
            s_used[e] = 1;
        }
    }
    __syncthreads();
    int base = tid * 5;
    int loc[5];
    int cnt = 0;
#pragma unroll
    for (int u = 0; u < 5; u++) {
        int e = base + u;
        int v = (e < TOTKEY) ? s_used[e] : 0;
        loc[u] = v;
        cnt += v;
    }
    int lane = tid & 31, wid = tid >> 5;
    int x = cnt;
    for (int d = 1; d < 32; d <<= 1) {
        int y = __shfl_up_sync(0xffffffffu, x, d);
        if (lane >= d) x += y;
    }
    if (lane == 31) wsum[wid] = x;
    __syncthreads();
    if (wid == 0) {
        int w = wsum[lane];
        for (int d = 1; d < 32; d <<= 1) {
            int y = __shfl_up_sync(0xffffffffu, w, d);
            if (lane >= d) w += y;
        }
        wsum[lane] = w;
    }
    __syncthreads();
    int off = x - cnt + (wid ? wsum[wid - 1] : 0);
#pragma unroll
    for (int u = 0; u < 5; u++) {
        int e = base + u;
        if (e < TOTKEY) {
            if (loc[u]) {
                s_used[e] = off;
                g_keyOfRow[off] = e;
                off++;
            } else {
                s_used[e] = -1;
            }
        }
    }
    if (tid == 1023) g_M[0] = off;
    __syncthreads();
#pragma unroll
    for (int u = 0; u < 2; u++) {
        int idx = tid + u * 1024;
        if (idx < NTOT) g_roiRow[idx] = s_used[s_key[idx]];
    }
}

// ---------------- kernel 1: pool (strided over rows) ----------------
#define POOL_GRID 256
__global__ void __launch_bounds__(256) pool_kernel() {
    const int tid = threadIdx.x;
    const int M = g_M[0];
    for (int r = blockIdx.x; r < M; r += POOL_GRID) {
        int e = g_keyOfRow[r];
        int b = e / NKEY;
        int kid = e % NKEY;
        float* Arow = g_A + (size_t)r * DD;
        if (kid == 2401) {
            for (int k = tid; k < DD; k += 256) Arow[k] = 0.f;
            continue;
        }
        int yf = kid % 7;
        int xf = (kid / 7) % 7;
        int yi = (kid / 49) % 7;
        int xi = kid / 343;
        int wx = xf + 1 - xi, wy = yf + 1 - yi;
        int bx[8], by[8];
#pragma unroll
        for (int ii = 0; ii < 8; ii++) {
            bx[ii] = xi + (ii * wx) / 7;
            by[ii] = yi + (ii * wy) / 7;
        }
        for (int c = tid; c < CC; c += 256) {
            const float* f = g_F + ((size_t)b * CC + c) * 49;
            float v[49];
#pragma unroll
            for (int p = 0; p < 49; p++) v[p] = f[p];
#pragma unroll
            for (int i = 0; i < 7; i++) {
                int x0 = bx[i], x1 = bx[i + 1];
#pragma unroll
                for (int j = 0; j < 7; j++) {
                    int y0 = by[j], y1 = by[j + 1];
                    float m = -3.0e38f;
                    for (int xx = x0; xx < x1; xx++)
                        for (int yy = y0; yy < y1; yy++)
                            m = fmaxf(m, v[xx * 7 + yy]);
                    Arow[c * 49 + i * 7 + j] = (x1 > x0 && y1 > y0) ? m : 0.f;
                }
            }
        }
    }
}

// ---------------- kernel 2: split-K tf32 GEMM, register-prefetch pipeline ----------------
#define GM_BM 128
#define SASTR 36
__global__ void __launch_bounds__(512) gemm_tc_kernel(const float* __restrict__ w1) {
    const int M = g_M[0];
    const int mBase = blockIdx.y * GM_BM;
    if (mBase >= M) return;
    const int k0 = blockIdx.x * KCHUNK;
    __shared__ __align__(16) float sA[GM_BM * SASTR];
    __shared__ __align__(16) float sW[H1 * SASTR];
    const int tid = threadIdx.x;
    const int lane = tid & 31, wid = tid >> 5;
    const int warpM = wid & 3;
    const int warpN = wid >> 2;
    const int nfBase = (warpN == 0) ? 0 : 1 + warpN * 6;
    const int nfCnt = (warpN == 0) ? 7 : 6;

    // staging indices (fixed per thread)
    const int arr0 = tid >> 3,           akq0 = tid & 7;          // A idx tid
    const int arr1 = (tid + 512) >> 3,   akq1 = tid & 7;          // A idx tid+512
    const int wn0 = tid >> 3,            wkq0 = tid & 7;
    const int wn1 = (tid + 512) >> 3,    wkq1 = tid & 7;
    const int wn2 = (tid + 1024) >> 3,   wkq2 = tid & 7;
    const bool w3v = tid < 64;
    const int wn3 = (tid + 1536) >> 3,   wkq3 = tid & 7;

    float4 pa0, pa1, pw0, pw1, pw2, pw3;

    auto fetch = [&](int slab) {
        int g0 = mBase + arr0, g1 = mBase + arr1;
        pa0 = make_float4(0.f, 0.f, 0.f, 0.f);
        pa1 = make_float4(0.f, 0.f, 0.f, 0.f);
        if (g0 < M) pa0 = *reinterpret_cast<const float4*>(&g_A[(size_t)g0 * DD + k0 + slab * 32 + akq0 * 4]);
        if (g1 < M) pa1 = *reinterpret_cast<const float4*>(&g_A[(size_t)g1 * DD + k0 + slab * 32 + akq1 * 4]);
        pw0 = *reinterpret_cast<const float4*>(&w1[(size_t)wn0 * DD + k0 + slab * 32 + wkq0 * 4]);
        pw1 = *reinterpret_cast<const float4*>(&w1[(size_t)wn1 * DD + k0 + slab * 32 + wkq1 * 4]);
        pw2 = *reinterpret_cast<const float4*>(&w1[(size_t)wn2 * DD + k0 + slab * 32 + wkq2 * 4]);
        if (w3v) pw3 = *reinterpret_cast<const float4*>(&w1[(size_t)wn3 * DD + k0 + slab * 32 + wkq3 * 4]);
    };
    auto commit = [&]() {
        *reinterpret_cast<float4*>(&sA[arr0 * SASTR + akq0 * 4]) = pa0;
        *reinterpret_cast<float4*>(&sA[arr1 * SASTR + akq1 * 4]) = pa1;
        *reinterpret_cast<float4*>(&sW[wn0 * SASTR + wkq0 * 4]) = pw0;
        *reinterpret_cast<float4*>(&sW[wn1 * SASTR + wkq1 * 4]) = pw1;
        *reinterpret_cast<float4*>(&sW[wn2 * SASTR + wkq2 * 4]) = pw2;
        if (w3v) *reinterpret_cast<float4*>(&sW[wn3 * SASTR + wkq3 * 4]) = pw3;
    };

    float acc[2][7][4];
#pragma unroll
    for (int f = 0; f < 2; f++)
#pragma unroll
        for (int i = 0; i < 7; i++)
#pragma unroll
            for (int j = 0; j < 4; j++) acc[f][i][j] = 0.f;

    fetch(0);
    commit();
    __syncthreads();

    for (int slab = 0; slab < 16; slab++) {
        if (slab + 1 < 16) fetch(slab + 1);   // global loads overlap MMA below
#pragma unroll
        for (int ks = 0; ks < 4; ks++) {
            int kcol = ks * 8 + (lane & 3);
            int row0 = warpM * 32 + (lane >> 2);
            uint32_t a00 = __float_as_uint(sA[row0 * SASTR + kcol]);
            uint32_t a01 = __float_as_uint(sA[(row0 + 8) * SASTR + kcol]);
            uint32_t a02 = __float_as_uint(sA[row0 * SASTR + kcol + 4]);
            uint32_t a03 = __float_as_uint(sA[(row0 + 8) * SASTR + kcol + 4]);
            uint32_t a10 = __float_as_uint(sA[(row0 + 16) * SASTR + kcol]);
            uint32_t a11 = __float_as_uint(sA[(row0 + 24) * SASTR + kcol]);
            uint32_t a12 = __float_as_uint(sA[(row0 + 16) * SASTR + kcol + 4]);
            uint32_t a13 = __float_as_uint(sA[(row0 + 24) * SASTR + kcol + 4]);
#pragma unroll
            for (int nf = 0; nf < 7; nf++) {
                if (nf < nfCnt) {
                    int n0 = (nfBase + nf) * 8 + (lane >> 2);
                    uint32_t b0 = __float_as_uint(sW[n0 * SASTR + kcol]);
                    uint32_t b1 = __float_as_uint(sW[n0 * SASTR + kcol + 4]);
                    mma_tf32(acc[0][nf][0], acc[0][nf][1], acc[0][nf][2], acc[0][nf][3],
                             a00, a01, a02, a03, b0, b1);
                    mma_tf32(acc[1][nf][0], acc[1][nf][1], acc[1][nf][2], acc[1][nf][3],
                             a10, a11, a12, a13, b0, b1);
                }
            }
        }
        if (slab + 1 < 16) {
            __syncthreads();   // everyone done reading current smem
            commit();
            __syncthreads();   // next slab visible
        }
    }
#pragma unroll
    for (int f = 0; f < 2; f++) {
        int rowA = mBase + warpM * 32 + f * 16 + (lane >> 2);
        int rowB = rowA + 8;
#pragma unroll
        for (int nf = 0; nf < 7; nf++) {
            if (nf < nfCnt) {
                int col = (nfBase + nf) * 8 + (lane & 3) * 2;
                if (rowA < MAXROWS)
                    *reinterpret_cast<float2*>(&g_P[((size_t)rowA * KSPLIT + blockIdx.x) * H1 + col]) =
                        make_float2(acc[f][nf][0], acc[f][nf][1]);
                if (rowB < MAXROWS)
                    *reinterpret_cast<float2*>(&g_P[((size_t)rowB * KSPLIT + blockIdx.x) * H1 + col]) =
                        make_float2(acc[f][nf][2], acc[f][nf][3]);
            }
        }
    }
}

// ---------------- kernel 3: fused reduce + MLP (strided rows, 2-way ILP) ----------------
#define MLP_GRID 256
__global__ void __launch_bounds__(256) mlp_kernel(const float* __restrict__ b1,
                                                  const float* __restrict__ w2, const float* __restrict__ b2,
                                                  const float* __restrict__ w3, const float* __restrict__ b3,
                                                  const float* __restrict__ w4, const float* __restrict__ b4) {
    const int M = g_M[0];
    __shared__ float h1s[H1];
    __shared__ float h2s[H2];
    const int t = threadIdx.x;
    const int lane = t & 31, wid = t >> 5;
    for (int r = blockIdx.x; r < M; r += MLP_GRID) {
        // split-K reduce over contiguous [r][ks][H1]
        {
            const float* Pr = g_P + (size_t)r * KSPLIT * H1;
            if (t < H1) {
                float s = b1[t];
#pragma unroll
                for (int ks = 0; ks < KSPLIT; ks++)
                    s += Pr[ks * H1 + t];
                h1s[t] = fmaxf(s, 0.f);
            }
        }
        __syncthreads();
        // h2: two interleaved outputs per warp iteration
        for (int j = wid; j < H2; j += 16) {
            int j2 = j + 8;
            bool v2 = j2 < H2;
            const float* wr0 = w2 + j * H1;
            const float* wr1 = w2 + (v2 ? j2 : j) * H1;
            float s0 = 0.f, s1 = 0.f;
#pragma unroll
            for (int k = lane; k < H1; k += 32) {
                float hk = h1s[k];
                s0 += wr0[k] * hk;
                s1 += wr1[k] * hk;
            }
#pragma unroll
            for (int d = 16; d > 0; d >>= 1) {
                s0 += __shfl_xor_sync(0xffffffffu, s0, d);
                s1 += __shfl_xor_sync(0xffffffffu, s1, d);
            }
            if (lane == 0) {
                h2s[j] = fmaxf(s0 + b2[j], 0.f);
                if (v2) h2s[j2] = fmaxf(s1 + b2[j2], 0.f);
            }
        }
        __syncthreads();
        // out85: two interleaved outputs per warp iteration
        for (int q = wid; q < 85; q += 16) {
            int q2 = q + 8;
            bool v2 = q2 < 85;
            const float *wr0, *wr1;
            float bias0, bias1 = 0.f;
            if (q < KC) { wr0 = w3 + q * H2;        bias0 = b3[q]; }
            else        { wr0 = w4 + (q - KC) * H2; bias0 = b4[q - KC]; }
            if (v2) {
                if (q2 < KC) { wr1 = w3 + q2 * H2;        bias1 = b3[q2]; }
                else         { wr1 = w4 + (q2 - KC) * H2; bias1 = b4[q2 - KC]; }
            } else wr1 = wr0;
            float s0 = 0.f, s1 = 0.f;
#pragma unroll
            for (int k = lane; k < H2; k += 32) {
                float hk = h2s[k];
                s0 += wr0[k] * hk;
                s1 += wr1[k] * hk;
            }
#pragma unroll
            for (int d = 16; d > 0; d >>= 1) {
                s0 += __shfl_xor_sync(0xffffffffu, s0, d);
                s1 += __shfl_xor_sync(0xffffffffu, s1, d);
            }
            if (lane == 0) {
                g_out85[r * 85 + q] = s0 + bias0;
                if (v2) g_out85[r * 85 + q2] = s1 + bias1;
            }
        }
        __syncthreads();
    }
}

// ---------------- kernel 4: scatter ----------------
__global__ void scatter_kernel(float* __restrict__ out) {
    int idx = blockIdx.x * blockDim.x + threadIdx.x;
    if (idx >= NTOT * 85) return;
    int bn = idx / 85;
    int q = idx % 85;
    int r = g_roiRow[bn];
    float val = g_out85[r * 85 + q];
    if (q < KC) {
        out[bn * KC + q] = val;                                        // z1
    } else {
        int k = (q - KC) / KC, cls = (q - KC) % KC;
        int b = bn / NROI, n = bn % NROI;
        out[NTOT * KC + (((b * 4 + k) * NROI + n) * KC + cls)] = val;  // z3
    }
}

// ---------------- launch ----------------
extern "C" void kernel_launch(void* const* d_in, const int* in_sizes, int n_in,
                              void* d_out, int out_size) {
    const float* cfeats = (const float*)d_in[0];
    const float* regcls = (const float*)d_in[1];
    const float* wan    = (const float*)d_in[2];
    const float* han    = (const float*)d_in[3];
    const float* xan    = (const float*)d_in[4];
    const float* yan    = (const float*)d_in[5];
    const float* w1     = (const float*)d_in[6];
    const float* b1     = (const float*)d_in[7];
    const float* w2     = (const float*)d_in[8];
    const float* b2     = (const float*)d_in[9];
    const float* w3     = (const float*)d_in[10];
    const float* b3     = (const float*)d_in[11];
    const float* w4     = (const float*)d_in[12];
    const float* b4     = (const float*)d_in[13];
    float* out = (float*)d_out;

    fused0_kernel<<<1, 1024>>>(regcls, wan, han, xan, yan, cfeats);
    pool_kernel<<<POOL_GRID, 256>>>();
    {
        dim3 grid(KSPLIT, (MAXROWS + GM_BM - 1) / GM_BM);
        gemm_tc_kernel<<<grid, 512>>>(w1);
    }
    mlp_kernel<<<MLP_GRID, 256>>>(b1, w2, b2, w3, b3, w4, b4);
    scatter_kernel<<<(NTOT * 85 + 255) / 256, 256>>>(out);
}